// round 15
// baseline (speedup 1.0000x reference)
#include <cuda_runtime.h>
#include <cuda_fp16.h>

#define RES    512
#define FEAT   32
#define NPLANE 6
#define PAIRS  (FEAT / 2)   // 16 half2 per texel

// Channel-last fp16 scratch: [6][512][512][16] half2 = 100.7 MB.
__device__ __half2 g_scratch[(size_t)NPLANE * RES * RES * PAIRS];

// K1: transpose {0,1,3}, dual 4-row tiles: 16 wtiles x 64 hgroups x 3 = 3072 blocks
#define TB1 3072
// Fused K2: transpose {2,4,5}, 2-row tiles: 16 x 256 x 3 = 12288 blocks,
// interleaved with samplers via a mod-9 pattern (4 transpose : 5 sample).
#define TB2        12288
#define B_SPLIT    27648      // (TB2/4)*9
#define SB_PATTERN 15360      // (B_SPLIT/9)*5

// ---------------------------------------------------------------------------
// Single-tile transpose body (R12): 256 threads, ROWS h-rows, 32 chans x 32 w.
// Reads: float4/thread/row (warp = 4 channels x 128B). Writes: 128B/warp/row.
// ---------------------------------------------------------------------------
template<int P0, int P1, int P2, int ROWS>
__device__ __forceinline__ void transpose_body(const float* __restrict__ planes,
                                               int tb) {
    __shared__ float t[ROWS][32][33];

    const int tid = threadIdx.x;
    const int c   = tid >> 3;
    const int w4  = tid & 7;

    constexpr int HG = RES / ROWS;
    const int wt = tb & 15;
    const int hb = ((tb >> 4) % HG) * ROWS;
    const int pj = tb / (16 * HG);
    const int p  = (pj == 0) ? P0 : (pj == 1) ? P1 : P2;

    const size_t cs = (size_t)RES * RES;
    const float* __restrict__ src =
        planes + ((size_t)p * FEAT + c) * cs + (size_t)hb * RES + (wt * 32 + 4 * w4);

    float4 v[ROWS];
    #pragma unroll
    for (int r = 0; r < ROWS; ++r)
        v[r] = __ldcs((const float4*)(src + (size_t)r * RES));

    #pragma unroll
    for (int r = 0; r < ROWS; ++r) {
        t[r][c][4 * w4 + 0] = v[r].x;
        t[r][c][4 * w4 + 1] = v[r].y;
        t[r][c][4 * w4 + 2] = v[r].z;
        t[r][c][4 * w4 + 3] = v[r].w;
    }
    __syncthreads();

    const int tx   = tid & 31;
    const int ty   = tid >> 5;
    const int pair = tx & 15;
    #pragma unroll
    for (int r = 0; r < ROWS; ++r) {
        #pragma unroll
        for (int j = 0; j < 2; ++j) {
            const int wl  = (ty + 8 * j) * 2 + (tx >> 4);
            const int col = wt * 32 + wl;
            g_scratch[(((p * RES + (hb + r)) * RES) + col) * PAIRS + pair] =
                __floats2half2_rn(t[r][2 * pair][wl], t[r][2 * pair + 1][wl]);
        }
    }
}

// ---------------------------------------------------------------------------
// Dual-tile K1 body: two 4-row tiles per CTA (h-groups hg and hg+64), ALL 8
// float4 loads issued up front; one shared 17KB buffer reused sequentially.
// ---------------------------------------------------------------------------
template<int P0, int P1, int P2>
__device__ __forceinline__ void transpose_dual_body(const float* __restrict__ planes,
                                                    int tb) {
    constexpr int ROWS = 4;
    __shared__ float t[ROWS][32][33];

    const int tid = threadIdx.x;
    const int c   = tid >> 3;                     // channel 0..31
    const int w4  = tid & 7;                      // float4 slot 0..7

    const int wt = tb & 15;                       // 16 w tiles
    const int hg = (tb >> 4) & 63;                // 64 h groups
    const int pj = tb >> 10;                      // 0..2
    const int p  = (pj == 0) ? P0 : (pj == 1) ? P1 : P2;

    const int hb1 = hg * ROWS;                    // tile 1 rows
    const int hb2 = (hg + 64) * ROWS;             // tile 2 rows

    const size_t cs = (size_t)RES * RES;
    const float* __restrict__ base =
        planes + ((size_t)p * FEAT + c) * cs + (wt * 32 + 4 * w4);
    const float* __restrict__ src1 = base + (size_t)hb1 * RES;
    const float* __restrict__ src2 = base + (size_t)hb2 * RES;

    // Issue all 8 independent 16B loads back-to-back (MLP = 8).
    float4 v1[ROWS], v2[ROWS];
    #pragma unroll
    for (int r = 0; r < ROWS; ++r) v1[r] = __ldcs((const float4*)(src1 + (size_t)r * RES));
    #pragma unroll
    for (int r = 0; r < ROWS; ++r) v2[r] = __ldcs((const float4*)(src2 + (size_t)r * RES));

    const int tx   = tid & 31;
    const int ty   = tid >> 5;
    const int pair = tx & 15;

    // ---- tile 1 ----
    #pragma unroll
    for (int r = 0; r < ROWS; ++r) {
        t[r][c][4 * w4 + 0] = v1[r].x;
        t[r][c][4 * w4 + 1] = v1[r].y;
        t[r][c][4 * w4 + 2] = v1[r].z;
        t[r][c][4 * w4 + 3] = v1[r].w;
    }
    __syncthreads();
    #pragma unroll
    for (int r = 0; r < ROWS; ++r) {
        #pragma unroll
        for (int j = 0; j < 2; ++j) {
            const int wl  = (ty + 8 * j) * 2 + (tx >> 4);
            const int col = wt * 32 + wl;
            g_scratch[(((p * RES + (hb1 + r)) * RES) + col) * PAIRS + pair] =
                __floats2half2_rn(t[r][2 * pair][wl], t[r][2 * pair + 1][wl]);
        }
    }
    __syncthreads();   // WAR: all reads of tile-1 smem done before overwrite

    // ---- tile 2 ----
    #pragma unroll
    for (int r = 0; r < ROWS; ++r) {
        t[r][c][4 * w4 + 0] = v2[r].x;
        t[r][c][4 * w4 + 1] = v2[r].y;
        t[r][c][4 * w4 + 2] = v2[r].z;
        t[r][c][4 * w4 + 3] = v2[r].w;
    }
    __syncthreads();
    #pragma unroll
    for (int r = 0; r < ROWS; ++r) {
        #pragma unroll
        for (int j = 0; j < 2; ++j) {
            const int wl  = (ty + 8 * j) * 2 + (tx >> 4);
            const int col = wt * 32 + wl;
            g_scratch[(((p * RES + (hb2 + r)) * RES) + col) * PAIRS + pair] =
                __floats2half2_rn(t[r][2 * pair][wl], t[r][2 * pair + 1][wl]);
        }
    }
}

// ---------------------------------------------------------------------------
// Sample body: warp covers 8 points, 2 points/thread, 24 batched 8B gathers.
// G=0: planes {0,1,3} -> space. G=1: {2,4,5} -> spacetime.
// ---------------------------------------------------------------------------
template<int G>
__device__ __forceinline__ void sample_body(const float* __restrict__ pts,
                                            const float* __restrict__ tim,
                                            float* __restrict__ out,
                                            int N, int sbid) {
    const int gwarp = (sbid * 256 + (int)threadIdx.x) >> 5;
    const int lane  = threadIdx.x & 31;
    const int sub   = lane & 7;
    const int k     = lane >> 3;

    const int wpt = gwarp * 8;
    if (wpt >= N) return;

    int ptv[2];
    ptv[0] = wpt + k;
    ptv[1] = wpt + k + 4;

    const __half2* __restrict__ sc = g_scratch;

    int   a00[2][3], a01[2][3], a10[2][3], a11[2][3];
    float w00[2][3], w01[2][3], w10[2][3], w11[2][3];
    bool  valid[2];

    #pragma unroll
    for (int q = 0; q < 2; ++q) {
        const int pt = ptv[q];
        valid[q] = (pt < N);
        const int ps = valid[q] ? pt : 0;

        const float inv_b = 1.0f / 1.6f;
        const float dx = pts[ps * 3 + 0] * inv_b;
        const float dy = pts[ps * 3 + 1] * inv_b;
        const float dz = pts[ps * 3 + 2] * inv_b;

        float cx[3], cy[3];
        int pid[3];
        if (G == 0) {
            pid[0] = 0; cx[0] = dx; cy[0] = dy;
            pid[1] = 1; cx[1] = dx; cy[1] = dz;
            pid[2] = 3; cx[2] = dy; cy[2] = dz;
        } else {
            const float dt = tim[ps] * 2.0f - 1.0f;
            pid[0] = 2; cx[0] = dt; cy[0] = dx;
            pid[1] = 4; cx[1] = dt; cy[1] = dy;
            pid[2] = 5; cx[2] = dt; cy[2] = dz;
        }

        #pragma unroll
        for (int i = 0; i < 3; ++i) {
            const float x = fminf(fmaxf((cx[i] + 1.0f) * 0.5f * (float)(RES - 1), 0.0f), (float)(RES - 1));
            const float y = fminf(fmaxf((cy[i] + 1.0f) * 0.5f * (float)(RES - 1), 0.0f), (float)(RES - 1));
            const float x0f = floorf(x);
            const float y0f = floorf(y);
            const int x0 = (int)x0f;
            const int y0 = (int)y0f;
            const int x1 = min(x0 + 1, RES - 1);
            const int y1 = min(y0 + 1, RES - 1);
            const float wx = x - x0f;
            const float wy = y - y0f;

            const int pbase = pid[i] * (RES * RES * PAIRS) + 2 * sub;
            a00[q][i] = pbase + (y0 * RES + x0) * PAIRS;
            a01[q][i] = pbase + (y0 * RES + x1) * PAIRS;
            a10[q][i] = pbase + (y1 * RES + x0) * PAIRS;
            a11[q][i] = pbase + (y1 * RES + x1) * PAIRS;
            w00[q][i] = (1.0f - wx) * (1.0f - wy);
            w01[q][i] = wx * (1.0f - wy);
            w10[q][i] = (1.0f - wx) * wy;
            w11[q][i] = wx * wy;
        }
    }

    uint2 c00[2][3], c01[2][3], c10[2][3], c11[2][3];
    #pragma unroll
    for (int q = 0; q < 2; ++q) {
        #pragma unroll
        for (int i = 0; i < 3; ++i) {
            c00[q][i] = __ldg((const uint2*)(sc + a00[q][i]));
            c01[q][i] = __ldg((const uint2*)(sc + a01[q][i]));
            c10[q][i] = __ldg((const uint2*)(sc + a10[q][i]));
            c11[q][i] = __ldg((const uint2*)(sc + a11[q][i]));
        }
    }

    #pragma unroll
    for (int q = 0; q < 2; ++q) {
        float f[3][4];
        #pragma unroll
        for (int i = 0; i < 3; ++i) {
            const float2 v00a = __half22float2(*(const __half2*)&c00[q][i].x);
            const float2 v00b = __half22float2(*(const __half2*)&c00[q][i].y);
            const float2 v01a = __half22float2(*(const __half2*)&c01[q][i].x);
            const float2 v01b = __half22float2(*(const __half2*)&c01[q][i].y);
            const float2 v10a = __half22float2(*(const __half2*)&c10[q][i].x);
            const float2 v10b = __half22float2(*(const __half2*)&c10[q][i].y);
            const float2 v11a = __half22float2(*(const __half2*)&c11[q][i].x);
            const float2 v11b = __half22float2(*(const __half2*)&c11[q][i].y);

            f[i][0] = v00a.x * w00[q][i] + v01a.x * w01[q][i] + v10a.x * w10[q][i] + v11a.x * w11[q][i];
            f[i][1] = v00a.y * w00[q][i] + v01a.y * w01[q][i] + v10a.y * w10[q][i] + v11a.y * w11[q][i];
            f[i][2] = v00b.x * w00[q][i] + v01b.x * w01[q][i] + v10b.x * w10[q][i] + v11b.x * w11[q][i];
            f[i][3] = v00b.y * w00[q][i] + v01b.y * w01[q][i] + v10b.y * w10[q][i] + v11b.y * w11[q][i];
        }

        float4 r;
        r.x = f[0][0] * f[1][0] * f[2][0];
        r.y = f[0][1] * f[1][1] * f[2][1];
        r.z = f[0][2] * f[1][2] * f[2][2];
        r.w = f[0][3] * f[1][3] * f[2][3];

        if (valid[q]) {
            float4* __restrict__ o = (float4*)out + (size_t)G * N * 8 + (size_t)ptv[q] * 8 + sub;
            __stcs(o, r);
        }
    }
}

// K1: transpose planes {0,1,3}, dual 4-row tiles (MLP=8, smem unchanged).
__global__ void __launch_bounds__(256)
transpose_first_kernel(const float* __restrict__ planes) {
    transpose_dual_body<0, 1, 3>(planes, blockIdx.x);
}

// K2: role-interleaved fused kernel (R12 pattern).
//   bid < B_SPLIT: r=bid%9; r<4 -> transpose{2,4,5} tile (bid/9)*4+r
//                           else -> sample0 block (bid/9)*5+(r-4)
//   bid >= B_SPLIT: sample0 block SB_PATTERN + (bid - B_SPLIT)
__global__ void __launch_bounds__(256)
fused_kernel(const float* __restrict__ planes,
             const float* __restrict__ pts,
             const float* __restrict__ tim,
             float* __restrict__ out,
             int N) {
    const int bid = blockIdx.x;
    if (bid < B_SPLIT) {
        const int q = bid / 9;
        const int r = bid % 9;
        if (r < 4) {
            transpose_body<2, 4, 5, 2>(planes, q * 4 + r);
        } else {
            sample_body<0>(pts, tim, out, N, q * 5 + (r - 4));
        }
    } else {
        sample_body<0>(pts, tim, out, N, SB_PATTERN + (bid - B_SPLIT));
    }
}

// K3: sample group 1.
__global__ void __launch_bounds__(256)
sample1_kernel(const float* __restrict__ pts,
               const float* __restrict__ tim,
               float* __restrict__ out,
               int N) {
    sample_body<1>(pts, tim, out, N, blockIdx.x);
}

extern "C" void kernel_launch(void* const* d_in, const int* in_sizes, int n_in,
                              void* d_out, int out_size) {
    const float* pts    = (const float*)d_in[0];
    const float* tim    = (const float*)d_in[1];
    const float* planes = (const float*)d_in[2];

    const int N = in_sizes[0] / 3;

    const int warps   = (N + 7) / 8;
    const int sblocks = (warps * 32 + 255) / 256;

    transpose_first_kernel<<<TB1, 256>>>(planes);

    int extra = sblocks - SB_PATTERN;
    if (extra < 0) extra = 0;
    fused_kernel<<<B_SPLIT + extra, 256>>>(planes, pts, tim, (float*)d_out, N);

    sample1_kernel<<<sblocks, 256>>>(pts, tim, (float*)d_out, N);
}

// round 16
// speedup vs baseline: 1.0005x; 1.0005x over previous
#include <cuda_runtime.h>
#include <cuda_fp16.h>

#define RES    512
#define FEAT   32
#define NPLANE 6
#define PAIRS  (FEAT / 2)   // 16 half2 per texel

// Channel-last fp16 scratch: [6][512][512][16] half2 = 100.7 MB.
__device__ __half2 g_scratch[(size_t)NPLANE * RES * RES * PAIRS];

// K1: transpose {0,1,3}, dual 4-row tiles: 16 wtiles x 64 hgroups x 3 = 3072 blocks
#define TB1 3072
// Fused K2: transpose {2,4,5}, 2-row tiles: 16 x 256 x 3 = 12288 blocks,
// interleaved with samplers via a mod-9 pattern (4 transpose : 5 sample).
#define TB2        12288
#define B_SPLIT    27648      // (TB2/4)*9
#define SB_PATTERN 15360      // (B_SPLIT/9)*5

// ---------------------------------------------------------------------------
// Single-tile transpose body: 256 threads, ROWS h-rows, 32 chans x 32 w.
// Reads: float4/thread/row (warp = 4 channels x 128B). Writes: 128B/warp/row.
// ---------------------------------------------------------------------------
template<int P0, int P1, int P2, int ROWS>
__device__ __forceinline__ void transpose_body(const float* __restrict__ planes,
                                               int tb) {
    __shared__ float t[ROWS][32][33];

    const int tid = threadIdx.x;
    const int c   = tid >> 3;
    const int w4  = tid & 7;

    constexpr int HG = RES / ROWS;
    const int wt = tb & 15;
    const int hb = ((tb >> 4) % HG) * ROWS;
    const int pj = tb / (16 * HG);
    const int p  = (pj == 0) ? P0 : (pj == 1) ? P1 : P2;

    const size_t cs = (size_t)RES * RES;
    const float* __restrict__ src =
        planes + ((size_t)p * FEAT + c) * cs + (size_t)hb * RES + (wt * 32 + 4 * w4);

    float4 v[ROWS];
    #pragma unroll
    for (int r = 0; r < ROWS; ++r)
        v[r] = __ldcs((const float4*)(src + (size_t)r * RES));

    #pragma unroll
    for (int r = 0; r < ROWS; ++r) {
        t[r][c][4 * w4 + 0] = v[r].x;
        t[r][c][4 * w4 + 1] = v[r].y;
        t[r][c][4 * w4 + 2] = v[r].z;
        t[r][c][4 * w4 + 3] = v[r].w;
    }
    __syncthreads();

    const int tx   = tid & 31;
    const int ty   = tid >> 5;
    const int pair = tx & 15;
    #pragma unroll
    for (int r = 0; r < ROWS; ++r) {
        #pragma unroll
        for (int j = 0; j < 2; ++j) {
            const int wl  = (ty + 8 * j) * 2 + (tx >> 4);
            const int col = wt * 32 + wl;
            g_scratch[(((p * RES + (hb + r)) * RES) + col) * PAIRS + pair] =
                __floats2half2_rn(t[r][2 * pair][wl], t[r][2 * pair + 1][wl]);
        }
    }
}

// ---------------------------------------------------------------------------
// Dual-tile K1 body: two 4-row tiles per CTA (h-groups hg and hg+64), all 8
// float4 loads issued up front (MLP=8); one 17KB buffer reused sequentially.
// ---------------------------------------------------------------------------
template<int P0, int P1, int P2>
__device__ __forceinline__ void transpose_dual_body(const float* __restrict__ planes,
                                                    int tb) {
    constexpr int ROWS = 4;
    __shared__ float t[ROWS][32][33];

    const int tid = threadIdx.x;
    const int c   = tid >> 3;
    const int w4  = tid & 7;

    const int wt = tb & 15;
    const int hg = (tb >> 4) & 63;
    const int pj = tb >> 10;
    const int p  = (pj == 0) ? P0 : (pj == 1) ? P1 : P2;

    const int hb1 = hg * ROWS;
    const int hb2 = (hg + 64) * ROWS;

    const size_t cs = (size_t)RES * RES;
    const float* __restrict__ base =
        planes + ((size_t)p * FEAT + c) * cs + (wt * 32 + 4 * w4);
    const float* __restrict__ src1 = base + (size_t)hb1 * RES;
    const float* __restrict__ src2 = base + (size_t)hb2 * RES;

    float4 v1[ROWS], v2[ROWS];
    #pragma unroll
    for (int r = 0; r < ROWS; ++r) v1[r] = __ldcs((const float4*)(src1 + (size_t)r * RES));
    #pragma unroll
    for (int r = 0; r < ROWS; ++r) v2[r] = __ldcs((const float4*)(src2 + (size_t)r * RES));

    const int tx   = tid & 31;
    const int ty   = tid >> 5;
    const int pair = tx & 15;

    // ---- tile 1 ----
    #pragma unroll
    for (int r = 0; r < ROWS; ++r) {
        t[r][c][4 * w4 + 0] = v1[r].x;
        t[r][c][4 * w4 + 1] = v1[r].y;
        t[r][c][4 * w4 + 2] = v1[r].z;
        t[r][c][4 * w4 + 3] = v1[r].w;
    }
    __syncthreads();
    #pragma unroll
    for (int r = 0; r < ROWS; ++r) {
        #pragma unroll
        for (int j = 0; j < 2; ++j) {
            const int wl  = (ty + 8 * j) * 2 + (tx >> 4);
            const int col = wt * 32 + wl;
            g_scratch[(((p * RES + (hb1 + r)) * RES) + col) * PAIRS + pair] =
                __floats2half2_rn(t[r][2 * pair][wl], t[r][2 * pair + 1][wl]);
        }
    }
    __syncthreads();   // WAR: tile-1 smem fully read before overwrite

    // ---- tile 2 ----
    #pragma unroll
    for (int r = 0; r < ROWS; ++r) {
        t[r][c][4 * w4 + 0] = v2[r].x;
        t[r][c][4 * w4 + 1] = v2[r].y;
        t[r][c][4 * w4 + 2] = v2[r].z;
        t[r][c][4 * w4 + 3] = v2[r].w;
    }
    __syncthreads();
    #pragma unroll
    for (int r = 0; r < ROWS; ++r) {
        #pragma unroll
        for (int j = 0; j < 2; ++j) {
            const int wl  = (ty + 8 * j) * 2 + (tx >> 4);
            const int col = wt * 32 + wl;
            g_scratch[(((p * RES + (hb2 + r)) * RES) + col) * PAIRS + pair] =
                __floats2half2_rn(t[r][2 * pair][wl], t[r][2 * pair + 1][wl]);
        }
    }
}

// ---------------------------------------------------------------------------
// Sample body: warp covers 8 points, 2 points/thread, 24 batched 8B gathers.
// G=0: planes {0,1,3} -> space. G=1: {2,4,5} -> spacetime.
// ---------------------------------------------------------------------------
template<int G>
__device__ __forceinline__ void sample_body(const float* __restrict__ pts,
                                            const float* __restrict__ tim,
                                            float* __restrict__ out,
                                            int N, int sbid) {
    const int gwarp = (sbid * 256 + (int)threadIdx.x) >> 5;
    const int lane  = threadIdx.x & 31;
    const int sub   = lane & 7;
    const int k     = lane >> 3;

    const int wpt = gwarp * 8;
    if (wpt >= N) return;

    int ptv[2];
    ptv[0] = wpt + k;
    ptv[1] = wpt + k + 4;

    const __half2* __restrict__ sc = g_scratch;

    int   a00[2][3], a01[2][3], a10[2][3], a11[2][3];
    float w00[2][3], w01[2][3], w10[2][3], w11[2][3];
    bool  valid[2];

    #pragma unroll
    for (int q = 0; q < 2; ++q) {
        const int pt = ptv[q];
        valid[q] = (pt < N);
        const int ps = valid[q] ? pt : 0;

        const float inv_b = 1.0f / 1.6f;
        const float dx = pts[ps * 3 + 0] * inv_b;
        const float dy = pts[ps * 3 + 1] * inv_b;
        const float dz = pts[ps * 3 + 2] * inv_b;

        float cx[3], cy[3];
        int pid[3];
        if (G == 0) {
            pid[0] = 0; cx[0] = dx; cy[0] = dy;
            pid[1] = 1; cx[1] = dx; cy[1] = dz;
            pid[2] = 3; cx[2] = dy; cy[2] = dz;
        } else {
            const float dt = tim[ps] * 2.0f - 1.0f;
            pid[0] = 2; cx[0] = dt; cy[0] = dx;
            pid[1] = 4; cx[1] = dt; cy[1] = dy;
            pid[2] = 5; cx[2] = dt; cy[2] = dz;
        }

        #pragma unroll
        for (int i = 0; i < 3; ++i) {
            const float x = fminf(fmaxf((cx[i] + 1.0f) * 0.5f * (float)(RES - 1), 0.0f), (float)(RES - 1));
            const float y = fminf(fmaxf((cy[i] + 1.0f) * 0.5f * (float)(RES - 1), 0.0f), (float)(RES - 1));
            const float x0f = floorf(x);
            const float y0f = floorf(y);
            const int x0 = (int)x0f;
            const int y0 = (int)y0f;
            const int x1 = min(x0 + 1, RES - 1);
            const int y1 = min(y0 + 1, RES - 1);
            const float wx = x - x0f;
            const float wy = y - y0f;

            const int pbase = pid[i] * (RES * RES * PAIRS) + 2 * sub;
            a00[q][i] = pbase + (y0 * RES + x0) * PAIRS;
            a01[q][i] = pbase + (y0 * RES + x1) * PAIRS;
            a10[q][i] = pbase + (y1 * RES + x0) * PAIRS;
            a11[q][i] = pbase + (y1 * RES + x1) * PAIRS;
            w00[q][i] = (1.0f - wx) * (1.0f - wy);
            w01[q][i] = wx * (1.0f - wy);
            w10[q][i] = (1.0f - wx) * wy;
            w11[q][i] = wx * wy;
        }
    }

    uint2 c00[2][3], c01[2][3], c10[2][3], c11[2][3];
    #pragma unroll
    for (int q = 0; q < 2; ++q) {
        #pragma unroll
        for (int i = 0; i < 3; ++i) {
            c00[q][i] = __ldg((const uint2*)(sc + a00[q][i]));
            c01[q][i] = __ldg((const uint2*)(sc + a01[q][i]));
            c10[q][i] = __ldg((const uint2*)(sc + a10[q][i]));
            c11[q][i] = __ldg((const uint2*)(sc + a11[q][i]));
        }
    }

    #pragma unroll
    for (int q = 0; q < 2; ++q) {
        float f[3][4];
        #pragma unroll
        for (int i = 0; i < 3; ++i) {
            const float2 v00a = __half22float2(*(const __half2*)&c00[q][i].x);
            const float2 v00b = __half22float2(*(const __half2*)&c00[q][i].y);
            const float2 v01a = __half22float2(*(const __half2*)&c01[q][i].x);
            const float2 v01b = __half22float2(*(const __half2*)&c01[q][i].y);
            const float2 v10a = __half22float2(*(const __half2*)&c10[q][i].x);
            const float2 v10b = __half22float2(*(const __half2*)&c10[q][i].y);
            const float2 v11a = __half22float2(*(const __half2*)&c11[q][i].x);
            const float2 v11b = __half22float2(*(const __half2*)&c11[q][i].y);

            f[i][0] = v00a.x * w00[q][i] + v01a.x * w01[q][i] + v10a.x * w10[q][i] + v11a.x * w11[q][i];
            f[i][1] = v00a.y * w00[q][i] + v01a.y * w01[q][i] + v10a.y * w10[q][i] + v11a.y * w11[q][i];
            f[i][2] = v00b.x * w00[q][i] + v01b.x * w01[q][i] + v10b.x * w10[q][i] + v11b.x * w11[q][i];
            f[i][3] = v00b.y * w00[q][i] + v01b.y * w01[q][i] + v10b.y * w10[q][i] + v11b.y * w11[q][i];
        }

        float4 r;
        r.x = f[0][0] * f[1][0] * f[2][0];
        r.y = f[0][1] * f[1][1] * f[2][1];
        r.z = f[0][2] * f[1][2] * f[2][2];
        r.w = f[0][3] * f[1][3] * f[2][3];

        if (valid[q]) {
            float4* __restrict__ o = (float4*)out + (size_t)G * N * 8 + (size_t)ptv[q] * 8 + sub;
            __stcs(o, r);
        }
    }
}

// K1: transpose planes {0,1,3}, dual 4-row tiles (MLP=8, 17KB smem).
__global__ void __launch_bounds__(256)
transpose_first_kernel(const float* __restrict__ planes) {
    transpose_dual_body<0, 1, 3>(planes, blockIdx.x);
}

// K2: role-interleaved fused kernel (R12 pattern — measured best).
//   bid < B_SPLIT: r=bid%9; r<4 -> transpose{2,4,5} tile (bid/9)*4+r
//                           else -> sample0 block (bid/9)*5+(r-4)
//   bid >= B_SPLIT: sample0 block SB_PATTERN + (bid - B_SPLIT)
__global__ void __launch_bounds__(256)
fused_kernel(const float* __restrict__ planes,
             const float* __restrict__ pts,
             const float* __restrict__ tim,
             float* __restrict__ out,
             int N) {
    const int bid = blockIdx.x;
    if (bid < B_SPLIT) {
        const int q = bid / 9;
        const int r = bid % 9;
        if (r < 4) {
            transpose_body<2, 4, 5, 2>(planes, q * 4 + r);
        } else {
            sample_body<0>(pts, tim, out, N, q * 5 + (r - 4));
        }
    } else {
        sample_body<0>(pts, tim, out, N, SB_PATTERN + (bid - B_SPLIT));
    }
}

// K3: sample group 1.
__global__ void __launch_bounds__(256)
sample1_kernel(const float* __restrict__ pts,
               const float* __restrict__ tim,
               float* __restrict__ out,
               int N) {
    sample_body<1>(pts, tim, out, N, blockIdx.x);
}

extern "C" void kernel_launch(void* const* d_in, const int* in_sizes, int n_in,
                              void* d_out, int out_size) {
    const float* pts    = (const float*)d_in[0];
    const float* tim    = (const float*)d_in[1];
    const float* planes = (const float*)d_in[2];

    const int N = in_sizes[0] / 3;

    const int warps   = (N + 7) / 8;
    const int sblocks = (warps * 32 + 255) / 256;

    transpose_first_kernel<<<TB1, 256>>>(planes);

    int extra = sblocks - SB_PATTERN;
    if (extra < 0) extra = 0;
    fused_kernel<<<B_SPLIT + extra, 256>>>(planes, pts, tim, (float*)d_out, N);

    sample1_kernel<<<sblocks, 256>>>(pts, tim, (float*)d_out, N);
}

// round 17
// speedup vs baseline: 1.0194x; 1.0189x over previous
#include <cuda_runtime.h>
#include <cuda_fp16.h>

#define RES    512
#define FEAT   32
#define NPLANE 6
#define PAIRS  (FEAT / 2)   // 16 half2 per texel

// Channel-last fp16 scratch: [6][512][512][16] half2 = 100.7 MB.
__device__ __half2 g_scratch[(size_t)NPLANE * RES * RES * PAIRS];

// K1: transpose {0,1,3}, dual 4-row tiles: 16 wtiles x 64 hgroup-pairs x 3 = 3072
#define TB1 3072
// Fused K2: transpose {2,4,5}, dual 2-row tiles: 16 x 128 x 3 = 6144 blocks,
// interleaved with samplers via a mod-7 pattern (2 transpose : 5 sample).
#define B_SPLIT    21504      // (6144/2)*7
#define SB_PATTERN 15360      // (B_SPLIT/7)*5

// ---------------------------------------------------------------------------
// Dual-tile transpose body: two ROWS-row tiles per CTA (h-groups hg, hg+HGH),
// ALL 2*ROWS float4 loads issued up front (max MLP at constant smem); one
// smem buffer reused sequentially. Reads: float4/thread/row (warp = 4
// channels x 128B coalesced). Writes: 128B contiguous per warp per row.
// ---------------------------------------------------------------------------
template<int P0, int P1, int P2, int ROWS>
__device__ __forceinline__ void transpose_dual_body(const float* __restrict__ planes,
                                                    int tb) {
    __shared__ float t[ROWS][32][33];
    constexpr int HGH = RES / ROWS / 2;           // h-group pairs per plane col

    const int tid = threadIdx.x;
    const int c   = tid >> 3;                     // channel 0..31
    const int w4  = tid & 7;                      // float4 slot 0..7

    const int wt = tb & 15;                       // 16 w tiles
    const int hg = (tb >> 4) % HGH;
    const int pj = tb / (16 * HGH);               // 0..2
    const int p  = (pj == 0) ? P0 : (pj == 1) ? P1 : P2;

    const int hb1 = hg * ROWS;
    const int hb2 = (hg + HGH) * ROWS;

    const size_t cs = (size_t)RES * RES;
    const float* __restrict__ base =
        planes + ((size_t)p * FEAT + c) * cs + (wt * 32 + 4 * w4);
    const float* __restrict__ src1 = base + (size_t)hb1 * RES;
    const float* __restrict__ src2 = base + (size_t)hb2 * RES;

    // Issue all 2*ROWS independent 16B loads back-to-back.
    float4 v1[ROWS], v2[ROWS];
    #pragma unroll
    for (int r = 0; r < ROWS; ++r) v1[r] = __ldcs((const float4*)(src1 + (size_t)r * RES));
    #pragma unroll
    for (int r = 0; r < ROWS; ++r) v2[r] = __ldcs((const float4*)(src2 + (size_t)r * RES));

    const int tx   = tid & 31;
    const int ty   = tid >> 5;
    const int pair = tx & 15;

    // ---- tile 1 ----
    #pragma unroll
    for (int r = 0; r < ROWS; ++r) {
        t[r][c][4 * w4 + 0] = v1[r].x;
        t[r][c][4 * w4 + 1] = v1[r].y;
        t[r][c][4 * w4 + 2] = v1[r].z;
        t[r][c][4 * w4 + 3] = v1[r].w;
    }
    __syncthreads();
    #pragma unroll
    for (int r = 0; r < ROWS; ++r) {
        #pragma unroll
        for (int j = 0; j < 2; ++j) {
            const int wl  = (ty + 8 * j) * 2 + (tx >> 4);
            const int col = wt * 32 + wl;
            g_scratch[(((p * RES + (hb1 + r)) * RES) + col) * PAIRS + pair] =
                __floats2half2_rn(t[r][2 * pair][wl], t[r][2 * pair + 1][wl]);
        }
    }
    __syncthreads();   // WAR: tile-1 smem fully read before overwrite

    // ---- tile 2 ----
    #pragma unroll
    for (int r = 0; r < ROWS; ++r) {
        t[r][c][4 * w4 + 0] = v2[r].x;
        t[r][c][4 * w4 + 1] = v2[r].y;
        t[r][c][4 * w4 + 2] = v2[r].z;
        t[r][c][4 * w4 + 3] = v2[r].w;
    }
    __syncthreads();
    #pragma unroll
    for (int r = 0; r < ROWS; ++r) {
        #pragma unroll
        for (int j = 0; j < 2; ++j) {
            const int wl  = (ty + 8 * j) * 2 + (tx >> 4);
            const int col = wt * 32 + wl;
            g_scratch[(((p * RES + (hb2 + r)) * RES) + col) * PAIRS + pair] =
                __floats2half2_rn(t[r][2 * pair][wl], t[r][2 * pair + 1][wl]);
        }
    }
}

// ---------------------------------------------------------------------------
// Sample body: warp covers 8 points, 2 points/thread, 24 batched 8B gathers.
// G=0: planes {0,1,3} -> space. G=1: {2,4,5} -> spacetime.
// ---------------------------------------------------------------------------
template<int G>
__device__ __forceinline__ void sample_body(const float* __restrict__ pts,
                                            const float* __restrict__ tim,
                                            float* __restrict__ out,
                                            int N, int sbid) {
    const int gwarp = (sbid * 256 + (int)threadIdx.x) >> 5;
    const int lane  = threadIdx.x & 31;
    const int sub   = lane & 7;
    const int k     = lane >> 3;

    const int wpt = gwarp * 8;
    if (wpt >= N) return;

    int ptv[2];
    ptv[0] = wpt + k;
    ptv[1] = wpt + k + 4;

    const __half2* __restrict__ sc = g_scratch;

    int   a00[2][3], a01[2][3], a10[2][3], a11[2][3];
    float w00[2][3], w01[2][3], w10[2][3], w11[2][3];
    bool  valid[2];

    #pragma unroll
    for (int q = 0; q < 2; ++q) {
        const int pt = ptv[q];
        valid[q] = (pt < N);
        const int ps = valid[q] ? pt : 0;

        const float inv_b = 1.0f / 1.6f;
        const float dx = pts[ps * 3 + 0] * inv_b;
        const float dy = pts[ps * 3 + 1] * inv_b;
        const float dz = pts[ps * 3 + 2] * inv_b;

        float cx[3], cy[3];
        int pid[3];
        if (G == 0) {
            pid[0] = 0; cx[0] = dx; cy[0] = dy;
            pid[1] = 1; cx[1] = dx; cy[1] = dz;
            pid[2] = 3; cx[2] = dy; cy[2] = dz;
        } else {
            const float dt = tim[ps] * 2.0f - 1.0f;
            pid[0] = 2; cx[0] = dt; cy[0] = dx;
            pid[1] = 4; cx[1] = dt; cy[1] = dy;
            pid[2] = 5; cx[2] = dt; cy[2] = dz;
        }

        #pragma unroll
        for (int i = 0; i < 3; ++i) {
            const float x = fminf(fmaxf((cx[i] + 1.0f) * 0.5f * (float)(RES - 1), 0.0f), (float)(RES - 1));
            const float y = fminf(fmaxf((cy[i] + 1.0f) * 0.5f * (float)(RES - 1), 0.0f), (float)(RES - 1));
            const float x0f = floorf(x);
            const float y0f = floorf(y);
            const int x0 = (int)x0f;
            const int y0 = (int)y0f;
            const int x1 = min(x0 + 1, RES - 1);
            const int y1 = min(y0 + 1, RES - 1);
            const float wx = x - x0f;
            const float wy = y - y0f;

            const int pbase = pid[i] * (RES * RES * PAIRS) + 2 * sub;
            a00[q][i] = pbase + (y0 * RES + x0) * PAIRS;
            a01[q][i] = pbase + (y0 * RES + x1) * PAIRS;
            a10[q][i] = pbase + (y1 * RES + x0) * PAIRS;
            a11[q][i] = pbase + (y1 * RES + x1) * PAIRS;
            w00[q][i] = (1.0f - wx) * (1.0f - wy);
            w01[q][i] = wx * (1.0f - wy);
            w10[q][i] = (1.0f - wx) * wy;
            w11[q][i] = wx * wy;
        }
    }

    uint2 c00[2][3], c01[2][3], c10[2][3], c11[2][3];
    #pragma unroll
    for (int q = 0; q < 2; ++q) {
        #pragma unroll
        for (int i = 0; i < 3; ++i) {
            c00[q][i] = __ldg((const uint2*)(sc + a00[q][i]));
            c01[q][i] = __ldg((const uint2*)(sc + a01[q][i]));
            c10[q][i] = __ldg((const uint2*)(sc + a10[q][i]));
            c11[q][i] = __ldg((const uint2*)(sc + a11[q][i]));
        }
    }

    #pragma unroll
    for (int q = 0; q < 2; ++q) {
        float f[3][4];
        #pragma unroll
        for (int i = 0; i < 3; ++i) {
            const float2 v00a = __half22float2(*(const __half2*)&c00[q][i].x);
            const float2 v00b = __half22float2(*(const __half2*)&c00[q][i].y);
            const float2 v01a = __half22float2(*(const __half2*)&c01[q][i].x);
            const float2 v01b = __half22float2(*(const __half2*)&c01[q][i].y);
            const float2 v10a = __half22float2(*(const __half2*)&c10[q][i].x);
            const float2 v10b = __half22float2(*(const __half2*)&c10[q][i].y);
            const float2 v11a = __half22float2(*(const __half2*)&c11[q][i].x);
            const float2 v11b = __half22float2(*(const __half2*)&c11[q][i].y);

            f[i][0] = v00a.x * w00[q][i] + v01a.x * w01[q][i] + v10a.x * w10[q][i] + v11a.x * w11[q][i];
            f[i][1] = v00a.y * w00[q][i] + v01a.y * w01[q][i] + v10a.y * w10[q][i] + v11a.y * w11[q][i];
            f[i][2] = v00b.x * w00[q][i] + v01b.x * w01[q][i] + v10b.x * w10[q][i] + v11b.x * w11[q][i];
            f[i][3] = v00b.y * w00[q][i] + v01b.y * w01[q][i] + v10b.y * w10[q][i] + v11b.y * w11[q][i];
        }

        float4 r;
        r.x = f[0][0] * f[1][0] * f[2][0];
        r.y = f[0][1] * f[1][1] * f[2][1];
        r.z = f[0][2] * f[1][2] * f[2][2];
        r.w = f[0][3] * f[1][3] * f[2][3];

        if (valid[q]) {
            float4* __restrict__ o = (float4*)out + (size_t)G * N * 8 + (size_t)ptv[q] * 8 + sub;
            __stcs(o, r);
        }
    }
}

// K1: transpose planes {0,1,3}, dual 4-row tiles (MLP=8, 17KB smem).
__global__ void __launch_bounds__(256)
transpose_first_kernel(const float* __restrict__ planes) {
    transpose_dual_body<0, 1, 3, 4>(planes, blockIdx.x);
}

// K2: role-interleaved fused kernel, dual-tile transposes (MLP=4, 8.4KB smem).
//   bid < B_SPLIT: r=bid%7; r<2 -> transpose{2,4,5} dual tile (bid/7)*2+r
//                           else -> sample0 block (bid/7)*5+(r-2)
//   bid >= B_SPLIT: sample0 block SB_PATTERN + (bid - B_SPLIT)
__global__ void __launch_bounds__(256)
fused_kernel(const float* __restrict__ planes,
             const float* __restrict__ pts,
             const float* __restrict__ tim,
             float* __restrict__ out,
             int N) {
    const int bid = blockIdx.x;
    if (bid < B_SPLIT) {
        const int q = bid / 7;
        const int r = bid % 7;
        if (r < 2) {
            transpose_dual_body<2, 4, 5, 2>(planes, q * 2 + r);
        } else {
            sample_body<0>(pts, tim, out, N, q * 5 + (r - 2));
        }
    } else {
        sample_body<0>(pts, tim, out, N, SB_PATTERN + (bid - B_SPLIT));
    }
}

// K3: sample group 1.
__global__ void __launch_bounds__(256)
sample1_kernel(const float* __restrict__ pts,
               const float* __restrict__ tim,
               float* __restrict__ out,
               int N) {
    sample_body<1>(pts, tim, out, N, blockIdx.x);
}

extern "C" void kernel_launch(void* const* d_in, const int* in_sizes, int n_in,
                              void* d_out, int out_size) {
    const float* pts    = (const float*)d_in[0];
    const float* tim    = (const float*)d_in[1];
    const float* planes = (const float*)d_in[2];

    const int N = in_sizes[0] / 3;

    const int warps   = (N + 7) / 8;
    const int sblocks = (warps * 32 + 255) / 256;

    transpose_first_kernel<<<TB1, 256>>>(planes);

    int extra = sblocks - SB_PATTERN;
    if (extra < 0) extra = 0;
    fused_kernel<<<B_SPLIT + extra, 256>>>(planes, pts, tim, (float*)d_out, N);

    sample1_kernel<<<sblocks, 256>>>(pts, tim, (float*)d_out, N);
}